// round 1
// baseline (speedup 1.0000x reference)
#include <cuda_runtime.h>

#define M_NODES 50000
#define K_NBR   32
#define DCH     256      // D_IN == D_OUT == 256
// floor(32 * 0.45) = 14 -> keep sorted[14..17], mean of 4

// Scratch for h = x @ W^T  (50000 x 256 fp32 = 51.2 MB, fits in L2)
__device__ float g_h[M_NODES * DCH];
__device__ int   g_nbr_is64;

// ---------------------------------------------------------------------------
// dtype sniffer: if nbrs is int64, every odd 32-bit word (hi half) is 0
// (indices in [0,50000)). If int32, odd words are random indices — P(all 32
// zero) ~ (1/50000)^32 ~ 0.
// ---------------------------------------------------------------------------
__global__ void detect_nbr_dtype(const int* __restrict__ words) {
    int w = words[2 * threadIdx.x + 1];
    unsigned m = __ballot_sync(0xffffffffu, w == 0);
    if (threadIdx.x == 0) g_nbr_is64 = (m == 0xffffffffu) ? 1 : 0;
}

// ---------------------------------------------------------------------------
// SGEMM: h[m][n] = sum_k x[m][k] * W[n][k]
// BM=128 BN=128 BK=16, 256 threads, 8x8 per thread.
// ---------------------------------------------------------------------------
__global__ void __launch_bounds__(256) sgemm_xWt(
    const float* __restrict__ A,   // x  [M, 256]
    const float* __restrict__ B)   // W  [256, 256]
{
    __shared__ float As[16][132];  // [k][m], padded
    __shared__ float Bs[16][132];  // [k][n], padded

    const int bm  = blockIdx.x * 128;
    const int bn  = blockIdx.y * 128;
    const int tid = threadIdx.x;
    const int tx  = tid & 15;      // n micro-tile
    const int ty  = tid >> 4;      // m micro-tile

    float acc[8][8];
#pragma unroll
    for (int i = 0; i < 8; i++)
#pragma unroll
        for (int j = 0; j < 8; j++) acc[i][j] = 0.0f;

#pragma unroll 1
    for (int kt = 0; kt < 256; kt += 16) {
        // load A tile 128x16 and B tile 128x16 (each: 512 float4, 2/thread)
#pragma unroll
        for (int l = 0; l < 2; l++) {
            int t   = tid + l * 256;        // 0..511
            int row = t >> 2;               // 0..127
            int k4  = (t & 3) * 4;          // 0,4,8,12

            float4 av = make_float4(0.f, 0.f, 0.f, 0.f);
            if (bm + row < M_NODES)
                av = *reinterpret_cast<const float4*>(&A[(size_t)(bm + row) * 256 + kt + k4]);
            As[k4 + 0][row] = av.x;
            As[k4 + 1][row] = av.y;
            As[k4 + 2][row] = av.z;
            As[k4 + 3][row] = av.w;

            float4 bv = *reinterpret_cast<const float4*>(&B[(size_t)(bn + row) * 256 + kt + k4]);
            Bs[k4 + 0][row] = bv.x;
            Bs[k4 + 1][row] = bv.y;
            Bs[k4 + 2][row] = bv.z;
            Bs[k4 + 3][row] = bv.w;
        }
        __syncthreads();

#pragma unroll
        for (int kk = 0; kk < 16; kk++) {
            float a[8], b[8];
            *reinterpret_cast<float4*>(&a[0]) = *reinterpret_cast<const float4*>(&As[kk][ty * 8 + 0]);
            *reinterpret_cast<float4*>(&a[4]) = *reinterpret_cast<const float4*>(&As[kk][ty * 8 + 4]);
            *reinterpret_cast<float4*>(&b[0]) = *reinterpret_cast<const float4*>(&Bs[kk][tx * 8 + 0]);
            *reinterpret_cast<float4*>(&b[4]) = *reinterpret_cast<const float4*>(&Bs[kk][tx * 8 + 4]);
#pragma unroll
            for (int i = 0; i < 8; i++)
#pragma unroll
                for (int j = 0; j < 8; j++)
                    acc[i][j] = fmaf(a[i], b[j], acc[i][j]);
        }
        __syncthreads();
    }

    // store 8x8 micro-tile (float4 x2 per row)
#pragma unroll
    for (int i = 0; i < 8; i++) {
        int m = bm + ty * 8 + i;
        if (m < M_NODES) {
            float* dst = &g_h[(size_t)m * 256 + bn + tx * 8];
            *reinterpret_cast<float4*>(dst + 0) = make_float4(acc[i][0], acc[i][1], acc[i][2], acc[i][3]);
            *reinterpret_cast<float4*>(dst + 4) = make_float4(acc[i][4], acc[i][5], acc[i][6], acc[i][7]);
        }
    }
}

// ---------------------------------------------------------------------------
// Gather + in-register bitonic sort of K=32 + trimmed mean.
// One block per node; thread d owns channel d. Warp reads 128B contiguous
// per neighbor row (coalesced); h rows are L2-resident.
// ---------------------------------------------------------------------------
__global__ void __launch_bounds__(256) gather_trim(
    const void* __restrict__ nbrs_raw,
    float* __restrict__ out)
{
    __shared__ int sn[K_NBR];  // pre-scaled row offsets

    const int node = blockIdx.x;
    const int tid  = threadIdx.x;

    if (tid < K_NBR) {
        long long idx;
        if (g_nbr_is64)
            idx = reinterpret_cast<const long long*>(nbrs_raw)[(size_t)node * K_NBR + tid];
        else
            idx = reinterpret_cast<const int*>(nbrs_raw)[(size_t)node * K_NBR + tid];
        sn[tid] = (int)idx * DCH;
    }
    __syncthreads();

    float v[K_NBR];
#pragma unroll
    for (int k = 0; k < K_NBR; k++)
        v[k] = __ldg(&g_h[sn[k] + tid]);

    // full in-register bitonic sort (ascending), 240 compare-exchanges
#pragma unroll
    for (int k = 2; k <= 32; k <<= 1) {
#pragma unroll
        for (int j = k >> 1; j > 0; j >>= 1) {
#pragma unroll
            for (int i = 0; i < 32; i++) {
                int ixj = i ^ j;
                if (ixj > i) {
                    bool up = ((i & k) == 0);
                    float a  = v[i], b = v[ixj];
                    float mn = fminf(a, b);
                    float mx = fmaxf(a, b);
                    v[i]   = up ? mn : mx;
                    v[ixj] = up ? mx : mn;
                }
            }
        }
    }

    out[(size_t)node * DCH + tid] = (v[14] + v[15] + v[16] + v[17]) * 0.25f;
}

// ---------------------------------------------------------------------------
extern "C" void kernel_launch(void* const* d_in, const int* in_sizes, int n_in,
                              void* d_out, int out_size)
{
    const float* x    = nullptr;
    const void*  nbrs = nullptr;
    const float* W    = nullptr;

    for (int i = 0; i < n_in; i++) {
        if      (in_sizes[i] == M_NODES * DCH)   x    = (const float*)d_in[i];
        else if (in_sizes[i] == M_NODES * K_NBR) nbrs = d_in[i];
        else if (in_sizes[i] == DCH * DCH)       W    = (const float*)d_in[i];
    }
    if (!x)    x    = (const float*)d_in[0];
    if (!nbrs) nbrs = d_in[1];
    if (!W)    W    = (const float*)d_in[2];

    detect_nbr_dtype<<<1, 32>>>((const int*)nbrs);

    dim3 ggrid((M_NODES + 127) / 128, 2);
    sgemm_xWt<<<ggrid, 256>>>(x, W);

    gather_trim<<<M_NODES, 256>>>(nbrs, (float*)d_out);
}